// round 14
// baseline (speedup 1.0000x reference)
#include <cuda_runtime.h>
#include <cuda_fp16.h>
#include <cstdint>
#include <cstddef>

#define NN   50000
#define EE   800000
#define DIN  128
#define DH   256
#define NBLK ((NN + 255) / 256)   // 196 scan blocks

// ---------------- scratch (device globals; no allocation allowed) ------------
__device__ float  g_dinv[NN];             // weighted in-degree -> rsqrt in place
__device__ int    g_count[NN];            // per-dst edge count
__device__ int    g_rowstart[NN + 1];     // CSR offsets
__device__ uint2  g_stage[EE];            // (src | dst<<16, rank)
__device__ int2   g_csr[EE];              // packed (src, w*dinv[s] as bits)
__device__ __half g_xh[NN * DIN];         // x in fp16
__device__ __half g_a1h[NN * DIN];        // A @ x in fp16 (GEMM input)
__device__ __half g_ph[NN * DIN];         // fused-GEMM output in fp16
__device__ __half g_w1h[DH * DIN];        // W1 fp16
__device__ __half g_w2h[DIN * DH];        // W2 fp16
__device__ int    g_is64;
__device__ int    g_ticket;                        // lookback ticket
__device__ unsigned long long g_state[NBLK];       // value<<2 | flag

// ---------------- prep: zero scratch + dtype detect + fp16 conversions -------
__global__ void prep_kernel(const int* __restrict__ raw,
                            const float* __restrict__ x,
                            const float* __restrict__ W1,
                            const float* __restrict__ W2,
                            float* __restrict__ deg,
                            int* __restrict__ cnt) {
    const int gtid   = blockIdx.x * blockDim.x + threadIdx.x;
    const int stride = gridDim.x * blockDim.x;

    for (int i = gtid; i < NN; i += stride) { deg[i] = 0.f; cnt[i] = 0; }
    for (int i = gtid; i < NBLK; i += stride) g_state[i] = 0ull;
    if (gtid == 0) g_ticket = 0;

    const int pairs = NN * DIN / 2;
    const float2* xin = (const float2*)x;
    __half2* xo = (__half2*)g_xh;
    for (int i = gtid; i < pairs; i += stride) {
        float2 v = xin[i];
        xo[i] = __floats2half2_rn(v.x, v.y);
    }
    const int wp = DH * DIN / 2;
    const float2* w1in = (const float2*)W1;
    const float2* w2in = (const float2*)W2;
    __half2* w1o = (__half2*)g_w1h;
    __half2* w2o = (__half2*)g_w2h;
    for (int i = gtid; i < wp; i += stride) {
        float2 a = w1in[i];
        float2 b = w2in[i];
        w1o[i] = __floats2half2_rn(a.x, a.y);
        w2o[i] = __floats2half2_rn(b.x, b.y);
    }

    if (blockIdx.x == 0) {
        int odd = (threadIdx.x < 128) ? raw[2 * threadIdx.x + 1] : 0;
        int any = __syncthreads_or(odd != 0);
        if (threadIdx.x == 0) g_is64 = any ? 0 : 1;
    }
}

// ---------------- index decode helper ----------------------------------------
__device__ __forceinline__ void decode_edge(const void* raw, int e, int i,
                                            int& s, int& d) {
    if (g_is64) {
        const long long* p = (const long long*)raw;
        s = (int)p[i];
        d = (int)p[(size_t)e + i];
    } else {
        const int* p = (const int*)raw;
        s = p[i];
        d = p[e + i];
    }
}

// ------- degree/counts + stage (src,dst,rank); 4 edges per thread ------------
__global__ void convert_deg_kernel(const void* __restrict__ raw,
                                   const float* __restrict__ w,
                                   float* __restrict__ deg,
                                   int* __restrict__ cnt,
                                   uint2* __restrict__ stage, int e) {
    int base = (blockIdx.x * blockDim.x + threadIdx.x) * 4;
    if (base >= e) return;
    int cntk = min(4, e - base);
#pragma unroll
    for (int k = 0; k < 4; k++) {
        if (k >= cntk) break;
        int s, d;
        decode_edge(raw, e, base + k, s, d);
        float wv = w[base + k];
        atomicAdd(&deg[d], wv);
        int r = atomicAdd(&cnt[d], 1);
        stage[base + k] =
            make_uint2((unsigned)s | ((unsigned)d << 16), (unsigned)r);
    }
}

// ---------------- single-pass lookback scan (+dinv fused) --------------------
__device__ __forceinline__ int block_scan_incl(int v) {
    const int lane = threadIdx.x & 31;
    const int warp = threadIdx.x >> 5;
    int s = v;
#pragma unroll
    for (int o = 1; o < 32; o <<= 1) {
        int t = __shfl_up_sync(0xFFFFFFFFu, s, o);
        if (lane >= o) s += t;
    }
    __shared__ int wsum[8];
    if (lane == 31) wsum[warp] = s;
    __syncthreads();
    if (warp == 0 && lane < 8) {
        int ws = wsum[lane];
#pragma unroll
        for (int o = 1; o < 8; o <<= 1) {
            int t = __shfl_up_sync(0xFFu, ws, o);
            if (lane >= o) ws += t;
        }
        wsum[lane] = ws;
    }
    __syncthreads();
    return s + (warp > 0 ? wsum[warp - 1] : 0);
}

__global__ void scan_lookback_kernel(const int* __restrict__ cnt,
                                     float* __restrict__ deg,   // -> dinv
                                     int* __restrict__ rowstart, int n) {
    __shared__ int s_bid, s_total, s_excl;
    if (threadIdx.x == 0) s_bid = atomicAdd(&g_ticket, 1);
    __syncthreads();
    const int bid = s_bid;
    const int idx = bid * 256 + threadIdx.x;

    int v = (idx < n) ? cnt[idx] : 0;
    int incl = block_scan_incl(v);
    if (threadIdx.x == 255) s_total = incl;
    __syncthreads();

    if (threadIdx.x == 0) {
        volatile unsigned long long* st = g_state;
        unsigned long long pkt =
            ((unsigned long long)s_total << 2) | (bid == 0 ? 2ull : 1ull);
        __threadfence();
        st[bid] = pkt;
        int excl = 0;
        if (bid > 0) {
            int j = bid - 1;
            while (true) {
                unsigned long long sv = st[j];
                unsigned f = (unsigned)(sv & 3ull);
                if (f == 0) continue;
                excl += (int)(sv >> 2);
                if (f == 2) break;
                j--;
            }
            unsigned long long pkt2 =
                ((unsigned long long)(excl + s_total) << 2) | 2ull;
            __threadfence();
            st[bid] = pkt2;
        }
        s_excl = excl;
    }
    __syncthreads();

    const int base = s_excl;
    if (idx < n) {
        rowstart[idx] = base + incl - v;
        deg[idx] = rsqrtf(deg[idx] + 1.0f);   // dinv fused (+1 = self-loop)
    }
    if (bid == (n + 255) / 256 - 1 && threadIdx.x == 255)
        rowstart[n] = base + s_total;
}

// --------- CSR fill: pos = rowstart[d] + rank; store (s, w*dinv[s]) ----------
__global__ void csr_fill_kernel(const uint2* __restrict__ stage,
                                const float* __restrict__ w,
                                const float* __restrict__ dinv,
                                const int* __restrict__ rowstart,
                                int2* __restrict__ csr, int e) {
    int base = (blockIdx.x * blockDim.x + threadIdx.x) * 4;
    if (base >= e) return;
    int cntk = min(4, e - base);

    uint2 st[4];
    float wv[4];
#pragma unroll
    for (int k = 0; k < 4; k++) {
        if (k < cntk) { st[k] = stage[base + k]; wv[k] = w[base + k]; }
        else          { st[k] = make_uint2(0u, 0u); wv[k] = 0.f; }
    }
    int   s[4], d[4];
    float ds[4];
    int   rs[4];
#pragma unroll
    for (int k = 0; k < 4; k++) {
        s[k] = (int)(st[k].x & 0xFFFFu);
        d[k] = (int)(st[k].x >> 16);
    }
#pragma unroll
    for (int k = 0; k < 4; k++) ds[k] = dinv[s[k]];
#pragma unroll
    for (int k = 0; k < 4; k++) rs[k] = rowstart[d[k]];
#pragma unroll
    for (int k = 0; k < 4; k++) {
        if (k < cntk)
            csr[rs[k] + (int)st[k].y] =
                make_int2(s[k], __float_as_int(wv[k] * ds[k]));
    }
}

// ---------------- CSR gather: half-warp per node, uint4 (LDG.128) loads ------
// 16 lanes per node; lane covers 8 features (uint4 = 8 halfs).
__device__ __forceinline__ void h8_acc(float acc[8], uint4 u, float nrm) {
    float2 f0 = __half22float2(*(__half2*)&u.x);
    float2 f1 = __half22float2(*(__half2*)&u.y);
    float2 f2 = __half22float2(*(__half2*)&u.z);
    float2 f3 = __half22float2(*(__half2*)&u.w);
    acc[0] = fmaf(f0.x, nrm, acc[0]); acc[1] = fmaf(f0.y, nrm, acc[1]);
    acc[2] = fmaf(f1.x, nrm, acc[2]); acc[3] = fmaf(f1.y, nrm, acc[3]);
    acc[4] = fmaf(f2.x, nrm, acc[4]); acc[5] = fmaf(f2.y, nrm, acc[5]);
    acc[6] = fmaf(f3.x, nrm, acc[6]); acc[7] = fmaf(f3.y, nrm, acc[7]);
}

// DO_LN=0: write fp16 (outb = __half*). DO_LN=1: LN, write fp32 (outb = float*)
template <int DO_LN>
__global__ __launch_bounds__(256)
void gather_kernel(const int* __restrict__ rowstart,
                   const int2* __restrict__ csr,
                   const float* __restrict__ dinv,
                   const __half* __restrict__ feat,
                   const float* __restrict__ b2,
                   const float* __restrict__ gamma,
                   const float* __restrict__ beta,
                   void* __restrict__ outb, int n) {
    const int node = (blockIdx.x * blockDim.x + threadIdx.x) >> 4;
    const int lane = threadIdx.x & 15;          // 16 lanes per node
    if (node >= n) return;

    const uint4* fp = (const uint4*)feat;       // row = 16 uint4
    float dv = dinv[node];

    float acc[8] = {0.f, 0.f, 0.f, 0.f, 0.f, 0.f, 0.f, 0.f};
    h8_acc(acc, fp[(size_t)node * 16 + lane], dv);

    const int beg = rowstart[node];
    const int end = rowstart[node + 1];

    int j = beg;
    for (; j + 3 < end; j += 4) {
        int2 e0 = csr[j], e1 = csr[j + 1], e2 = csr[j + 2], e3 = csr[j + 3];
        uint4 r0 = fp[(size_t)e0.x * 16 + lane];
        uint4 r1 = fp[(size_t)e1.x * 16 + lane];
        uint4 r2 = fp[(size_t)e2.x * 16 + lane];
        uint4 r3 = fp[(size_t)e3.x * 16 + lane];
        h8_acc(acc, r0, __int_as_float(e0.y));
        h8_acc(acc, r1, __int_as_float(e1.y));
        h8_acc(acc, r2, __int_as_float(e2.y));
        h8_acc(acc, r3, __int_as_float(e3.y));
    }
    for (; j < end; j++) {
        int2 e0 = csr[j];
        h8_acc(acc, fp[(size_t)e0.x * 16 + lane], __int_as_float(e0.y));
    }

#pragma unroll
    for (int q = 0; q < 8; q++) acc[q] *= dv;   // factored dinv[d]

    if (DO_LN) {
        const int c0 = lane * 8;
        float4 bb0 = *(const float4*)(b2 + c0);
        float4 bb1 = *(const float4*)(b2 + c0 + 4);
        acc[0] += bb0.x; acc[1] += bb0.y; acc[2] += bb0.z; acc[3] += bb0.w;
        acc[4] += bb1.x; acc[5] += bb1.y; acc[6] += bb1.z; acc[7] += bb1.w;

        float s = 0.f;
#pragma unroll
        for (int q = 0; q < 8; q++) s += acc[q];
#pragma unroll
        for (int o = 8; o > 0; o >>= 1) s += __shfl_xor_sync(0xFFFFFFFFu, s, o);
        float mu = s * (1.0f / DIN);

        float qv = 0.f;
#pragma unroll
        for (int q = 0; q < 8; q++) {
            acc[q] -= mu;
            qv += acc[q] * acc[q];
        }
#pragma unroll
        for (int o = 8; o > 0; o >>= 1) qv += __shfl_xor_sync(0xFFFFFFFFu, qv, o);
        float rstd = rsqrtf(qv * (1.0f / DIN) + 1e-5f);

        float4 g0 = *(const float4*)(gamma + c0);
        float4 g1 = *(const float4*)(gamma + c0 + 4);
        float4 t0 = *(const float4*)(beta + c0);
        float4 t1 = *(const float4*)(beta + c0 + 4);
        float4 o0, o1;
        o0.x = acc[0] * rstd * g0.x + t0.x;
        o0.y = acc[1] * rstd * g0.y + t0.y;
        o0.z = acc[2] * rstd * g0.z + t0.z;
        o0.w = acc[3] * rstd * g0.w + t0.w;
        o1.x = acc[4] * rstd * g1.x + t1.x;
        o1.y = acc[5] * rstd * g1.y + t1.y;
        o1.z = acc[6] * rstd * g1.z + t1.z;
        o1.w = acc[7] * rstd * g1.w + t1.w;
        float* op = (float*)outb + (size_t)node * DIN + c0;
        *(float4*)op       = o0;
        *(float4*)(op + 4) = o1;
    } else {
        __half2 h0 = __floats2half2_rn(acc[0], acc[1]);
        __half2 h1 = __floats2half2_rn(acc[2], acc[3]);
        __half2 h2 = __floats2half2_rn(acc[4], acc[5]);
        __half2 h3 = __floats2half2_rn(acc[6], acc[7]);
        uint4 pk = make_uint4(*(uint32_t*)&h0, *(uint32_t*)&h1,
                              *(uint32_t*)&h2, *(uint32_t*)&h3);
        ((uint4*)outb)[(size_t)node * 16 + lane] = pk;
    }
}

// ---------------- fused MLP: p = relu(A@W1^T + b1) @ W2^T --------------------
__device__ __forceinline__ void mma_f16(float c[4], const uint32_t a[4],
                                        const uint32_t b[2]) {
    asm volatile(
        "mma.sync.aligned.m16n8k16.row.col.f32.f16.f16.f32 "
        "{%0,%1,%2,%3}, {%4,%5,%6,%7}, {%8,%9}, {%0,%1,%2,%3};"
        : "+f"(c[0]), "+f"(c[1]), "+f"(c[2]), "+f"(c[3])
        : "r"(a[0]), "r"(a[1]), "r"(a[2]), "r"(a[3]), "r"(b[0]), "r"(b[1]));
}

#define AS_ST 68    // uints per row (64 data + 4 pad): 128-half rows
#define W2_ST 132   // uints per row (128 data + 4 pad): 256-half rows
#define SM_A  0
#define SM_W  (SM_A + 128 * AS_ST)
#define SM_H  (SM_W + 128 * W2_ST)
#define SM_TOTAL_U (SM_H + 128 * W2_ST)

__global__ __launch_bounds__(256, 1)
void fused_mlp_kernel(const __half* __restrict__ A,
                      const __half* __restrict__ W1,
                      const __half* __restrict__ W2,
                      const float* __restrict__ b1,
                      __half* __restrict__ P, int M) {
    extern __shared__ uint32_t sm[];
    uint32_t* A_s = sm + SM_A;
    uint32_t* W_s = sm + SM_W;
    uint32_t* H_s = sm + SM_H;

    const int tid  = threadIdx.x;
    const int lane = tid & 31;
    const int warp = tid >> 5;
    const int wm   = warp & 3;
    const int wn   = warp >> 2;
    const int gid  = lane >> 2;
    const int tig  = lane & 3;
    const int m0   = blockIdx.x * 128;

#pragma unroll
    for (int l = 0; l < 8; l++) {
        int idx = tid + l * 256;
        int row = idx >> 4;
        int q   = idx & 15;
        uint4 v = (m0 + row < M)
                ? *(const uint4*)(A + (size_t)(m0 + row) * DIN + q * 8)
                : make_uint4(0u, 0u, 0u, 0u);
        *(uint4*)&A_s[row * AS_ST + q * 4] = v;
    }

    for (int nh = 0; nh < 2; nh++) {
#pragma unroll
        for (int l = 0; l < 8; l++) {
            int idx = tid + l * 256;
            int row = idx >> 4;
            int q   = idx & 15;
            uint4 v = *(const uint4*)(W1 + (size_t)(nh * 128 + row) * DIN + q * 8);
            *(uint4*)&W_s[row * AS_ST + q * 4] = v;
        }
        __syncthreads();

        float acc[2][8][4];
#pragma unroll
        for (int i = 0; i < 2; i++)
#pragma unroll
            for (int j = 0; j < 8; j++)
#pragma unroll
                for (int q = 0; q < 4; q++) acc[i][j][q] = 0.f;

#pragma unroll
        for (int s = 0; s < 8; s++) {
            const int k2 = s * 8;
            uint32_t af[2][4];
#pragma unroll
            for (int mt = 0; mt < 2; mt++) {
                int rb = wm * 32 + mt * 16;
                af[mt][0] = A_s[(rb + gid) * AS_ST + k2 + tig];
                af[mt][1] = A_s[(rb + gid + 8) * AS_ST + k2 + tig];
                af[mt][2] = A_s[(rb + gid) * AS_ST + k2 + tig + 4];
                af[mt][3] = A_s[(rb + gid + 8) * AS_ST + k2 + tig + 4];
            }
            uint32_t bf[8][2];
#pragma unroll
            for (int ntl = 0; ntl < 8; ntl++) {
                int col = wn * 64 + ntl * 8 + gid;
                bf[ntl][0] = W_s[col * AS_ST + k2 + tig];
                bf[ntl][1] = W_s[col * AS_ST + k2 + tig + 4];
            }
#pragma unroll
            for (int mt = 0; mt < 2; mt++)
#pragma unroll
                for (int ntl = 0; ntl < 8; ntl++)
                    mma_f16(acc[mt][ntl], af[mt], bf[ntl]);
        }
        __syncthreads();

#pragma unroll
        for (int mt = 0; mt < 2; mt++) {
            int r0 = wm * 32 + mt * 16 + gid;
            int r1 = r0 + 8;
#pragma unroll
            for (int ntl = 0; ntl < 8; ntl++) {
                int colL = wn * 64 + ntl * 8 + tig * 2;
                int colG = nh * 128 + colL;
                float bx = b1[colG], by = b1[colG + 1];
                float2 v0 = make_float2(fmaxf(acc[mt][ntl][0] + bx, 0.f),
                                        fmaxf(acc[mt][ntl][1] + by, 0.f));
                float2 v1 = make_float2(fmaxf(acc[mt][ntl][2] + bx, 0.f),
                                        fmaxf(acc[mt][ntl][3] + by, 0.f));
                __half2 h0 = __floats2half2_rn(v0.x, v0.y);
                __half2 h1 = __floats2half2_rn(v1.x, v1.y);
                H_s[r0 * W2_ST + (colG >> 1)] = *(uint32_t*)&h0;
                H_s[r1 * W2_ST + (colG >> 1)] = *(uint32_t*)&h1;
            }
        }
    }

#pragma unroll
    for (int l = 0; l < 16; l++) {
        int idx = tid + l * 256;
        int row = idx >> 5;
        int q   = idx & 31;
        uint4 v = *(const uint4*)(W2 + (size_t)row * DH + q * 8);
        *(uint4*)&W_s[row * W2_ST + q * 4] = v;
    }
    __syncthreads();

    float acc2[2][8][4];
#pragma unroll
    for (int i = 0; i < 2; i++)
#pragma unroll
        for (int j = 0; j < 8; j++)
#pragma unroll
            for (int q = 0; q < 4; q++) acc2[i][j][q] = 0.f;

#pragma unroll
    for (int s = 0; s < 16; s++) {
        const int k2 = s * 8;
        uint32_t af[2][4];
#pragma unroll
        for (int mt = 0; mt < 2; mt++) {
            int rb = wm * 32 + mt * 16;
            af[mt][0] = H_s[(rb + gid) * W2_ST + k2 + tig];
            af[mt][1] = H_s[(rb + gid + 8) * W2_ST + k2 + tig];
            af[mt][2] = H_s[(rb + gid) * W2_ST + k2 + tig + 4];
            af[mt][3] = H_s[(rb + gid + 8) * W2_ST + k2 + tig + 4];
        }
        uint32_t bf[8][2];
#pragma unroll
        for (int ntl = 0; ntl < 8; ntl++) {
            int col = wn * 64 + ntl * 8 + gid;
            bf[ntl][0] = W_s[col * W2_ST + k2 + tig];
            bf[ntl][1] = W_s[col * W2_ST + k2 + tig + 4];
        }
#pragma unroll
        for (int mt = 0; mt < 2; mt++)
#pragma unroll
            for (int ntl = 0; ntl < 8; ntl++)
                mma_f16(acc2[mt][ntl], af[mt], bf[ntl]);
    }

#pragma unroll
    for (int mt = 0; mt < 2; mt++) {
        int row0 = m0 + wm * 32 + mt * 16 + gid;
        int row1 = row0 + 8;
#pragma unroll
        for (int ntl = 0; ntl < 8; ntl++) {
            int col = wn * 64 + ntl * 8 + tig * 2;
            __half2 h0 = __floats2half2_rn(acc2[mt][ntl][0], acc2[mt][ntl][1]);
            __half2 h1 = __floats2half2_rn(acc2[mt][ntl][2], acc2[mt][ntl][3]);
            if (row0 < M) *(__half2*)(P + (size_t)row0 * DIN + col) = h0;
            if (row1 < M) *(__half2*)(P + (size_t)row1 * DIN + col) = h1;
        }
    }
}

// -----------------------------------------------------------------------------
extern "C" void kernel_launch(void* const* d_in, const int* in_sizes, int n_in,
                              void* d_out, int out_size) {
    const float* x     = (const float*)d_in[0];
    const void*  ei    = d_in[1];
    const float* ew    = (const float*)d_in[2];
    const float* W1    = (const float*)d_in[3];
    const float* b1    = (const float*)d_in[4];
    const float* W2    = (const float*)d_in[5];
    const float* b2    = (const float*)d_in[6];
    const float* gamma = (const float*)d_in[7];
    const float* beta  = (const float*)d_in[8];
    float*       out   = (float*)d_out;

    float *dinv;
    __half *xh, *a1h, *ph, *w1h, *w2h;
    int *cnt, *rowstart;
    uint2 *stage;
    int2 *csr;
    cudaGetSymbolAddress((void**)&dinv,     g_dinv);
    cudaGetSymbolAddress((void**)&xh,       g_xh);
    cudaGetSymbolAddress((void**)&a1h,      g_a1h);
    cudaGetSymbolAddress((void**)&ph,       g_ph);
    cudaGetSymbolAddress((void**)&w1h,      g_w1h);
    cudaGetSymbolAddress((void**)&w2h,      g_w2h);
    cudaGetSymbolAddress((void**)&cnt,      g_count);
    cudaGetSymbolAddress((void**)&rowstart, g_rowstart);
    cudaGetSymbolAddress((void**)&stage,    g_stage);
    cudaGetSymbolAddress((void**)&csr,      g_csr);

    const int n = NN, e = EE;
    const int smem_bytes = SM_TOTAL_U * 4;
    static bool attr_set = false;
    if (!attr_set) {
        cudaFuncSetAttribute(fused_mlp_kernel,
                             cudaFuncAttributeMaxDynamicSharedMemorySize,
                             smem_bytes);
        attr_set = true;
    }

    // 1. prep: zero scratch, detect dtype, x/W1/W2 -> fp16 (single stream)
    prep_kernel<<<1024, 256>>>((const int*)ei, x, W1, W2, dinv, cnt);

    // 2. degree + counts + stage (src,dst,rank) — 4 edges/thread
    convert_deg_kernel<<<(e / 4 + 255) / 256, 256>>>(ei, ew, dinv, cnt, stage, e);

    // 3. single-pass scan (+dinv)
    scan_lookback_kernel<<<NBLK, 256>>>(cnt, dinv, rowstart, n);

    // 4. CSR fill: pos = rowstart + rank — 4 edges/thread
    csr_fill_kernel<<<(e / 4 + 255) / 256, 256>>>(stage, ew, dinv, rowstart, csr, e);

    // 5. agg1 = A_norm @ x  (half-warp gather -> fp16)
    gather_kernel<0><<<(n * 16 + 255) / 256, 256>>>(rowstart, csr, dinv, xh,
                                                    nullptr, nullptr, nullptr,
                                                    a1h, n);

    // 6. p = relu(agg1 @ W1^T + b1) @ W2^T   (fused MLP)
    fused_mlp_kernel<<<(n + 127) / 128, 256, smem_bytes>>>(a1h, w1h, w2h, b1,
                                                           ph, n);

    // 7. out = LN(A_norm @ p + b2) * gamma + beta
    gather_kernel<1><<<(n * 16 + 255) / 256, 256>>>(rowstart, csr, dinv, ph,
                                                    b2, gamma, beta, out, n);
}

// round 15
// speedup vs baseline: 1.0830x; 1.0830x over previous
#include <cuda_runtime.h>
#include <cuda_fp16.h>
#include <cstdint>
#include <cstddef>

#define NN   50000
#define EE   800000
#define DIN  128
#define DH   256
#define NBLK ((NN + 255) / 256)   // 196 scan blocks

#define DEG_MASK  ((1ull << 40) - 1ull)
#define CNT_ONE   (1ull << 40)
#define DEG_SCALE 16777216.0f     // 2^24

// ---------------- scratch (device globals; no allocation allowed) ------------
__device__ unsigned long long g_packed[NN];   // cnt<<40 | fixedpoint(deg)
__device__ float  g_dinv[NN];             // rsqrt(deg+1)
__device__ int    g_rowstart[NN + 1];     // CSR offsets
__device__ uint2  g_stage[EE];            // (src | dst<<16, rank)
__device__ int2   g_csr[EE];              // packed (src, w*dinv[s] as bits)
__device__ __half g_xh[NN * DIN];         // x in fp16
__device__ __half g_a1h[NN * DIN];        // A @ x in fp16 (GEMM input)
__device__ __half g_ph[NN * DIN];         // fused-GEMM output in fp16
__device__ __half g_w1h[DH * DIN];        // W1 fp16
__device__ __half g_w2h[DIN * DH];        // W2 fp16
__device__ int    g_is64;
__device__ int    g_ticket;                        // lookback ticket
__device__ unsigned long long g_state[NBLK];       // value<<2 | flag

// ---------------- prep: zero scratch + dtype detect + fp16 conversions -------
__global__ void prep_kernel(const int* __restrict__ raw,
                            const float* __restrict__ x,
                            const float* __restrict__ W1,
                            const float* __restrict__ W2) {
    const int gtid   = blockIdx.x * blockDim.x + threadIdx.x;
    const int stride = gridDim.x * blockDim.x;

    for (int i = gtid; i < NN; i += stride) g_packed[i] = 0ull;
    for (int i = gtid; i < NBLK; i += stride) g_state[i] = 0ull;
    if (gtid == 0) g_ticket = 0;

    const int pairs = NN * DIN / 2;
    const float2* xin = (const float2*)x;
    __half2* xo = (__half2*)g_xh;
    for (int i = gtid; i < pairs; i += stride) {
        float2 v = xin[i];
        xo[i] = __floats2half2_rn(v.x, v.y);
    }
    const int wp = DH * DIN / 2;
    const float2* w1in = (const float2*)W1;
    const float2* w2in = (const float2*)W2;
    __half2* w1o = (__half2*)g_w1h;
    __half2* w2o = (__half2*)g_w2h;
    for (int i = gtid; i < wp; i += stride) {
        float2 a = w1in[i];
        float2 b = w2in[i];
        w1o[i] = __floats2half2_rn(a.x, a.y);
        w2o[i] = __floats2half2_rn(b.x, b.y);
    }

    if (blockIdx.x == 0) {
        int odd = (threadIdx.x < 128) ? raw[2 * threadIdx.x + 1] : 0;
        int any = __syncthreads_or(odd != 0);
        if (threadIdx.x == 0) g_is64 = any ? 0 : 1;
    }
}

// ---------------- index decode helper ----------------------------------------
__device__ __forceinline__ void decode_edge(const void* raw, int e, int i,
                                            int& s, int& d) {
    if (g_is64) {
        const long long* p = (const long long*)raw;
        s = (int)p[i];
        d = (int)p[(size_t)e + i];
    } else {
        const int* p = (const int*)raw;
        s = p[i];
        d = p[e + i];
    }
}

// ------- single packed atomic: deg (fixed-point) + count + rank --------------
__global__ void convert_deg_kernel(const void* __restrict__ raw,
                                   const float* __restrict__ w,
                                   unsigned long long* __restrict__ pk,
                                   uint2* __restrict__ stage, int e) {
    int base = (blockIdx.x * blockDim.x + threadIdx.x) * 2;
    if (base >= e) return;
    int s0, d0, s1 = 0, d1 = 0;
    decode_edge(raw, e, base, s0, d0);
    bool two = (base + 1 < e);
    if (two) decode_edge(raw, e, base + 1, s1, d1);
    float w0 = w[base];
    float w1 = two ? w[base + 1] : 0.f;

    unsigned long long c0 =
        CNT_ONE | (unsigned long long)(unsigned)__float2uint_rn(w0 * DEG_SCALE);
    unsigned long long o0 = atomicAdd(&pk[d0], c0);
    stage[base] = make_uint2((unsigned)s0 | ((unsigned)d0 << 16),
                             (unsigned)(o0 >> 40));
    if (two) {
        unsigned long long c1 =
            CNT_ONE | (unsigned long long)(unsigned)__float2uint_rn(w1 * DEG_SCALE);
        unsigned long long o1 = atomicAdd(&pk[d1], c1);
        stage[base + 1] = make_uint2((unsigned)s1 | ((unsigned)d1 << 16),
                                     (unsigned)(o1 >> 40));
    }
}

// ---------------- single-pass lookback scan (+dinv fused) --------------------
__device__ __forceinline__ int block_scan_incl(int v) {
    const int lane = threadIdx.x & 31;
    const int warp = threadIdx.x >> 5;
    int s = v;
#pragma unroll
    for (int o = 1; o < 32; o <<= 1) {
        int t = __shfl_up_sync(0xFFFFFFFFu, s, o);
        if (lane >= o) s += t;
    }
    __shared__ int wsum[8];
    if (lane == 31) wsum[warp] = s;
    __syncthreads();
    if (warp == 0 && lane < 8) {
        int ws = wsum[lane];
#pragma unroll
        for (int o = 1; o < 8; o <<= 1) {
            int t = __shfl_up_sync(0xFFu, ws, o);
            if (lane >= o) ws += t;
        }
        wsum[lane] = ws;
    }
    __syncthreads();
    return s + (warp > 0 ? wsum[warp - 1] : 0);
}

__global__ void scan_lookback_kernel(const unsigned long long* __restrict__ pk,
                                     float* __restrict__ dinv,
                                     int* __restrict__ rowstart, int n) {
    __shared__ int s_bid, s_total, s_excl;
    if (threadIdx.x == 0) s_bid = atomicAdd(&g_ticket, 1);
    __syncthreads();
    const int bid = s_bid;
    const int idx = bid * 256 + threadIdx.x;

    unsigned long long pv = (idx < n) ? pk[idx] : 0ull;
    int v = (int)(pv >> 40);
    int incl = block_scan_incl(v);
    if (threadIdx.x == 255) s_total = incl;
    __syncthreads();

    if (threadIdx.x == 0) {
        volatile unsigned long long* st = g_state;
        unsigned long long p =
            ((unsigned long long)s_total << 2) | (bid == 0 ? 2ull : 1ull);
        __threadfence();
        st[bid] = p;
        int excl = 0;
        if (bid > 0) {
            int j = bid - 1;
            while (true) {
                unsigned long long sv = st[j];
                unsigned f = (unsigned)(sv & 3ull);
                if (f == 0) continue;
                excl += (int)(sv >> 2);
                if (f == 2) break;
                j--;
            }
            unsigned long long p2 =
                ((unsigned long long)(excl + s_total) << 2) | 2ull;
            __threadfence();
            st[bid] = p2;
        }
        s_excl = excl;
    }
    __syncthreads();

    const int base = s_excl;
    if (idx < n) {
        rowstart[idx] = base + incl - v;
        float deg = (float)(pv & DEG_MASK) * (1.0f / DEG_SCALE);
        dinv[idx] = rsqrtf(deg + 1.0f);   // +1 = self-loop weight
    }
    if (bid == (n + 255) / 256 - 1 && threadIdx.x == 255)
        rowstart[n] = base + s_total;
}

// --------- CSR fill: pos = rowstart[d] + rank; store (s, w*dinv[s]) ----------
__global__ void csr_fill_kernel(const uint2* __restrict__ stage,
                                const float* __restrict__ w,
                                const float* __restrict__ dinv,
                                const int* __restrict__ rowstart,
                                int2* __restrict__ csr, int e) {
    int base = (blockIdx.x * blockDim.x + threadIdx.x) * 2;
    if (base >= e) return;
    uint2 st0 = stage[base];
    bool two = (base + 1 < e);
    uint2 st1 = two ? stage[base + 1] : make_uint2(0u, 0u);
    float w0 = w[base];
    float w1 = two ? w[base + 1] : 0.f;

    int s0 = (int)(st0.x & 0xFFFFu), d0 = (int)(st0.x >> 16);
    int s1 = (int)(st1.x & 0xFFFFu), d1 = (int)(st1.x >> 16);
    float ds0 = dinv[s0];
    float ds1 = two ? dinv[s1] : 0.f;
    int rs0 = rowstart[d0];
    int rs1 = two ? rowstart[d1] : 0;

    csr[rs0 + (int)st0.y] = make_int2(s0, __float_as_int(w0 * ds0));
    if (two)
        csr[rs1 + (int)st1.y] = make_int2(s1, __float_as_int(w1 * ds1));
}

// ---------------- CSR gather over fp16 features, fp32 accumulate -------------
__device__ __forceinline__ float4 h4_to_f4(uint2 u) {
    __half2 a = *(__half2*)&u.x;
    __half2 b = *(__half2*)&u.y;
    float2 fa = __half22float2(a);
    float2 fb = __half22float2(b);
    return make_float4(fa.x, fa.y, fb.x, fb.y);
}

// DO_LN=0: write fp16 (outb = __half*). DO_LN=1: LN, write fp32 (outb = float*)
template <int DO_LN>
__global__ __launch_bounds__(256)
void gather_kernel(const int* __restrict__ rowstart,
                   const int2* __restrict__ csr,
                   const float* __restrict__ dinv,
                   const __half* __restrict__ feat,
                   const float* __restrict__ b2,
                   const float* __restrict__ gamma,
                   const float* __restrict__ beta,
                   void* __restrict__ outb, int n) {
    const int node = (blockIdx.x * blockDim.x + threadIdx.x) >> 5;
    const int lane = threadIdx.x & 31;
    if (node >= n) return;

    const uint2* fp = (const uint2*)feat;   // row = 32 uint2
    float dv = dinv[node];
    float4 acc = h4_to_f4(fp[node * 32 + lane]);
    acc.x *= dv; acc.y *= dv; acc.z *= dv; acc.w *= dv;

    const int beg = rowstart[node];
    const int end = rowstart[node + 1];

    int j = beg;
    for (; j + 3 < end; j += 4) {
        int2 e0 = csr[j], e1 = csr[j + 1], e2 = csr[j + 2], e3 = csr[j + 3];
        uint2 r0 = fp[e0.x * 32 + lane];
        uint2 r1 = fp[e1.x * 32 + lane];
        uint2 r2 = fp[e2.x * 32 + lane];
        uint2 r3 = fp[e3.x * 32 + lane];
        float4 v0 = h4_to_f4(r0), v1 = h4_to_f4(r1);
        float4 v2 = h4_to_f4(r2), v3 = h4_to_f4(r3);
        float n0 = __int_as_float(e0.y), n1 = __int_as_float(e1.y);
        float n2 = __int_as_float(e2.y), n3 = __int_as_float(e3.y);
        acc.x = fmaf(v0.x, n0, acc.x); acc.y = fmaf(v0.y, n0, acc.y);
        acc.z = fmaf(v0.z, n0, acc.z); acc.w = fmaf(v0.w, n0, acc.w);
        acc.x = fmaf(v1.x, n1, acc.x); acc.y = fmaf(v1.y, n1, acc.y);
        acc.z = fmaf(v1.z, n1, acc.z); acc.w = fmaf(v1.w, n1, acc.w);
        acc.x = fmaf(v2.x, n2, acc.x); acc.y = fmaf(v2.y, n2, acc.y);
        acc.z = fmaf(v2.z, n2, acc.z); acc.w = fmaf(v2.w, n2, acc.w);
        acc.x = fmaf(v3.x, n3, acc.x); acc.y = fmaf(v3.y, n3, acc.y);
        acc.w = fmaf(v3.w, n3, acc.w); acc.z = fmaf(v3.z, n3, acc.z);
    }
    for (; j < end; j++) {
        int2 e0 = csr[j];
        float4 v0 = h4_to_f4(fp[e0.x * 32 + lane]);
        float n0 = __int_as_float(e0.y);
        acc.x = fmaf(v0.x, n0, acc.x); acc.y = fmaf(v0.y, n0, acc.y);
        acc.z = fmaf(v0.z, n0, acc.z); acc.w = fmaf(v0.w, n0, acc.w);
    }

    acc.x *= dv; acc.y *= dv; acc.z *= dv; acc.w *= dv;

    if (DO_LN) {
        float4 bb = *(const float4*)(b2 + lane * 4);
        acc.x += bb.x; acc.y += bb.y; acc.z += bb.z; acc.w += bb.w;

        float s = acc.x + acc.y + acc.z + acc.w;
#pragma unroll
        for (int o = 16; o > 0; o >>= 1) s += __shfl_xor_sync(0xFFFFFFFFu, s, o);
        float mu = s * (1.0f / DIN);

        float dx = acc.x - mu, dy = acc.y - mu, dz = acc.z - mu, dw = acc.w - mu;
        float q = dx * dx + dy * dy + dz * dz + dw * dw;
#pragma unroll
        for (int o = 16; o > 0; o >>= 1) q += __shfl_xor_sync(0xFFFFFFFFu, q, o);
        float rstd = rsqrtf(q * (1.0f / DIN) + 1e-5f);

        float4 g  = *(const float4*)(gamma + lane * 4);
        float4 bt = *(const float4*)(beta + lane * 4);
        float4 o4;
        o4.x = dx * rstd * g.x + bt.x;
        o4.y = dy * rstd * g.y + bt.y;
        o4.z = dz * rstd * g.z + bt.z;
        o4.w = dw * rstd * g.w + bt.w;
        *(float4*)((float*)outb + (size_t)node * DIN + lane * 4) = o4;
    } else {
        __half2 h0 = __floats2half2_rn(acc.x, acc.y);
        __half2 h1 = __floats2half2_rn(acc.z, acc.w);
        uint2 pkt = make_uint2(*(uint32_t*)&h0, *(uint32_t*)&h1);
        ((uint2*)outb)[node * 32 + lane] = pkt;
    }
}

// ---------------- fused MLP: p = relu(A@W1^T + b1) @ W2^T --------------------
__device__ __forceinline__ void mma_f16(float c[4], const uint32_t a[4],
                                        const uint32_t b[2]) {
    asm volatile(
        "mma.sync.aligned.m16n8k16.row.col.f32.f16.f16.f32 "
        "{%0,%1,%2,%3}, {%4,%5,%6,%7}, {%8,%9}, {%0,%1,%2,%3};"
        : "+f"(c[0]), "+f"(c[1]), "+f"(c[2]), "+f"(c[3])
        : "r"(a[0]), "r"(a[1]), "r"(a[2]), "r"(a[3]), "r"(b[0]), "r"(b[1]));
}

#define AS_ST 68    // uints per row (64 data + 4 pad): 128-half rows
#define W2_ST 132   // uints per row (128 data + 4 pad): 256-half rows
#define SM_A  0
#define SM_W  (SM_A + 128 * AS_ST)
#define SM_H  (SM_W + 128 * W2_ST)
#define SM_TOTAL_U (SM_H + 128 * W2_ST)

__global__ __launch_bounds__(256, 1)
void fused_mlp_kernel(const __half* __restrict__ A,
                      const __half* __restrict__ W1,
                      const __half* __restrict__ W2,
                      const float* __restrict__ b1,
                      __half* __restrict__ P, int M) {
    extern __shared__ uint32_t sm[];
    uint32_t* A_s = sm + SM_A;
    uint32_t* W_s = sm + SM_W;
    uint32_t* H_s = sm + SM_H;

    const int tid  = threadIdx.x;
    const int lane = tid & 31;
    const int warp = tid >> 5;
    const int wm   = warp & 3;
    const int wn   = warp >> 2;
    const int gid  = lane >> 2;
    const int tig  = lane & 3;
    const int m0   = blockIdx.x * 128;

#pragma unroll
    for (int l = 0; l < 8; l++) {
        int idx = tid + l * 256;
        int row = idx >> 4;
        int q   = idx & 15;
        uint4 v = (m0 + row < M)
                ? *(const uint4*)(A + (size_t)(m0 + row) * DIN + q * 8)
                : make_uint4(0u, 0u, 0u, 0u);
        *(uint4*)&A_s[row * AS_ST + q * 4] = v;
    }

    for (int nh = 0; nh < 2; nh++) {
#pragma unroll
        for (int l = 0; l < 8; l++) {
            int idx = tid + l * 256;
            int row = idx >> 4;
            int q   = idx & 15;
            uint4 v = *(const uint4*)(W1 + (size_t)(nh * 128 + row) * DIN + q * 8);
            *(uint4*)&W_s[row * AS_ST + q * 4] = v;
        }
        __syncthreads();

        float acc[2][8][4];
#pragma unroll
        for (int i = 0; i < 2; i++)
#pragma unroll
            for (int j = 0; j < 8; j++)
#pragma unroll
                for (int q = 0; q < 4; q++) acc[i][j][q] = 0.f;

#pragma unroll
        for (int s = 0; s < 8; s++) {
            const int k2 = s * 8;
            uint32_t af[2][4];
#pragma unroll
            for (int mt = 0; mt < 2; mt++) {
                int rb = wm * 32 + mt * 16;
                af[mt][0] = A_s[(rb + gid) * AS_ST + k2 + tig];
                af[mt][1] = A_s[(rb + gid + 8) * AS_ST + k2 + tig];
                af[mt][2] = A_s[(rb + gid) * AS_ST + k2 + tig + 4];
                af[mt][3] = A_s[(rb + gid + 8) * AS_ST + k2 + tig + 4];
            }
            uint32_t bf[8][2];
#pragma unroll
            for (int ntl = 0; ntl < 8; ntl++) {
                int col = wn * 64 + ntl * 8 + gid;
                bf[ntl][0] = W_s[col * AS_ST + k2 + tig];
                bf[ntl][1] = W_s[col * AS_ST + k2 + tig + 4];
            }
#pragma unroll
            for (int mt = 0; mt < 2; mt++)
#pragma unroll
                for (int ntl = 0; ntl < 8; ntl++)
                    mma_f16(acc[mt][ntl], af[mt], bf[ntl]);
        }
        __syncthreads();

#pragma unroll
        for (int mt = 0; mt < 2; mt++) {
            int r0 = wm * 32 + mt * 16 + gid;
            int r1 = r0 + 8;
#pragma unroll
            for (int ntl = 0; ntl < 8; ntl++) {
                int colL = wn * 64 + ntl * 8 + tig * 2;
                int colG = nh * 128 + colL;
                float bx = b1[colG], by = b1[colG + 1];
                float2 v0 = make_float2(fmaxf(acc[mt][ntl][0] + bx, 0.f),
                                        fmaxf(acc[mt][ntl][1] + by, 0.f));
                float2 v1 = make_float2(fmaxf(acc[mt][ntl][2] + bx, 0.f),
                                        fmaxf(acc[mt][ntl][3] + by, 0.f));
                __half2 h0 = __floats2half2_rn(v0.x, v0.y);
                __half2 h1 = __floats2half2_rn(v1.x, v1.y);
                H_s[r0 * W2_ST + (colG >> 1)] = *(uint32_t*)&h0;
                H_s[r1 * W2_ST + (colG >> 1)] = *(uint32_t*)&h1;
            }
        }
    }

#pragma unroll
    for (int l = 0; l < 16; l++) {
        int idx = tid + l * 256;
        int row = idx >> 5;
        int q   = idx & 31;
        uint4 v = *(const uint4*)(W2 + (size_t)row * DH + q * 8);
        *(uint4*)&W_s[row * W2_ST + q * 4] = v;
    }
    __syncthreads();

    float acc2[2][8][4];
#pragma unroll
    for (int i = 0; i < 2; i++)
#pragma unroll
        for (int j = 0; j < 8; j++)
#pragma unroll
            for (int q = 0; q < 4; q++) acc2[i][j][q] = 0.f;

#pragma unroll
    for (int s = 0; s < 16; s++) {
        const int k2 = s * 8;
        uint32_t af[2][4];
#pragma unroll
        for (int mt = 0; mt < 2; mt++) {
            int rb = wm * 32 + mt * 16;
            af[mt][0] = H_s[(rb + gid) * W2_ST + k2 + tig];
            af[mt][1] = H_s[(rb + gid + 8) * W2_ST + k2 + tig];
            af[mt][2] = H_s[(rb + gid) * W2_ST + k2 + tig + 4];
            af[mt][3] = H_s[(rb + gid + 8) * W2_ST + k2 + tig + 4];
        }
        uint32_t bf[8][2];
#pragma unroll
        for (int ntl = 0; ntl < 8; ntl++) {
            int col = wn * 64 + ntl * 8 + gid;
            bf[ntl][0] = W_s[col * W2_ST + k2 + tig];
            bf[ntl][1] = W_s[col * W2_ST + k2 + tig + 4];
        }
#pragma unroll
        for (int mt = 0; mt < 2; mt++)
#pragma unroll
            for (int ntl = 0; ntl < 8; ntl++)
                mma_f16(acc2[mt][ntl], af[mt], bf[ntl]);
    }

#pragma unroll
    for (int mt = 0; mt < 2; mt++) {
        int row0 = m0 + wm * 32 + mt * 16 + gid;
        int row1 = row0 + 8;
#pragma unroll
        for (int ntl = 0; ntl < 8; ntl++) {
            int col = wn * 64 + ntl * 8 + tig * 2;
            __half2 h0 = __floats2half2_rn(acc2[mt][ntl][0], acc2[mt][ntl][1]);
            __half2 h1 = __floats2half2_rn(acc2[mt][ntl][2], acc2[mt][ntl][3]);
            if (row0 < M) *(__half2*)(P + (size_t)row0 * DIN + col) = h0;
            if (row1 < M) *(__half2*)(P + (size_t)row1 * DIN + col) = h1;
        }
    }
}

// -----------------------------------------------------------------------------
extern "C" void kernel_launch(void* const* d_in, const int* in_sizes, int n_in,
                              void* d_out, int out_size) {
    const float* x     = (const float*)d_in[0];
    const void*  ei    = d_in[1];
    const float* ew    = (const float*)d_in[2];
    const float* W1    = (const float*)d_in[3];
    const float* b1    = (const float*)d_in[4];
    const float* W2    = (const float*)d_in[5];
    const float* b2    = (const float*)d_in[6];
    const float* gamma = (const float*)d_in[7];
    const float* beta  = (const float*)d_in[8];
    float*       out   = (float*)d_out;

    float *dinv;
    __half *xh, *a1h, *ph, *w1h, *w2h;
    int *rowstart;
    uint2 *stage;
    int2 *csr;
    unsigned long long *pk;
    cudaGetSymbolAddress((void**)&pk,       g_packed);
    cudaGetSymbolAddress((void**)&dinv,     g_dinv);
    cudaGetSymbolAddress((void**)&xh,       g_xh);
    cudaGetSymbolAddress((void**)&a1h,      g_a1h);
    cudaGetSymbolAddress((void**)&ph,       g_ph);
    cudaGetSymbolAddress((void**)&w1h,      g_w1h);
    cudaGetSymbolAddress((void**)&w2h,      g_w2h);
    cudaGetSymbolAddress((void**)&rowstart, g_rowstart);
    cudaGetSymbolAddress((void**)&stage,    g_stage);
    cudaGetSymbolAddress((void**)&csr,      g_csr);

    const int n = NN, e = EE;
    const int smem_bytes = SM_TOTAL_U * 4;
    static bool attr_set = false;
    if (!attr_set) {
        cudaFuncSetAttribute(fused_mlp_kernel,
                             cudaFuncAttributeMaxDynamicSharedMemorySize,
                             smem_bytes);
        attr_set = true;
    }

    // 1. prep: zero scratch, detect dtype, x/W1/W2 -> fp16
    prep_kernel<<<1024, 256>>>((const int*)ei, x, W1, W2);

    // 2. packed degree+count+rank (single atomic) + stage — 2 edges/thread
    convert_deg_kernel<<<(e / 2 + 255) / 256, 256>>>(ei, ew, pk, stage, e);

    // 3. single-pass scan (+dinv from packed)
    scan_lookback_kernel<<<NBLK, 256>>>(pk, dinv, rowstart, n);

    // 4. CSR fill: pos = rowstart + rank — 2 edges/thread
    csr_fill_kernel<<<(e / 2 + 255) / 256, 256>>>(stage, ew, dinv, rowstart, csr, e);

    // 5. agg1 = A_norm @ x  (warp-per-node fp16 gather -> fp16)
    gather_kernel<0><<<(n * 32 + 255) / 256, 256>>>(rowstart, csr, dinv, xh,
                                                    nullptr, nullptr, nullptr,
                                                    a1h, n);

    // 6. p = relu(agg1 @ W1^T + b1) @ W2^T   (fused MLP)
    fused_mlp_kernel<<<(n + 127) / 128, 256, smem_bytes>>>(a1h, w1h, w2h, b1,
                                                           ph, n);

    // 7. out = LN(A_norm @ p + b2) * gamma + beta
    gather_kernel<1><<<(n * 32 + 255) / 256, 256>>>(rowstart, csr, dinv, ph,
                                                    b2, gamma, beta, out, n);
}